// round 1
// baseline (speedup 1.0000x reference)
#include <cuda_runtime.h>
#include <math.h>
#include <stdint.h>

// ---------------- problem constants ----------------
#define Bz   32
#define Sz   4
#define QLz  12
#define Dz   10
#define DLz  40
#define Vz   32000
#define Ez   256
#define Hqz  256
#define Hdz  256
#define Hsz  512

#define NQ     128            // B*S query sequences
#define NDOC   1280           // B*S*D doc sequences
#define QLANES 256            // fwd+bwd
#define DLANES 2560
#define NDEC   96             // B*(S-1)
#define TDEC   11             // QL-1
#define NEGF   (-1000000000.0f)

// ---------------- scratch (device globals; no allocation allowed) ------------
__device__ float g_qGates[QLz * QLANES * 4 * Hqz];          // 3.1M
__device__ float g_dGates[DLz * DLANES * 4 * Hdz];          // 104.9M (419MB)
__device__ float g_decGates[TDEC * NDEC * 4 * Hsz];         // 2.2M
__device__ float g_logits[NDEC * Vz];                       // 3.1M

__device__ float g_qh[QLANES * Hqz], g_qc[QLANES * Hqz], g_qrmax[QLANES * Hqz];
__device__ float g_dh[DLANES * Hdz], g_dc[DLANES * Hdz], g_drmax[DLANES * Hdz];
__device__ float g_encq[NQ * 2 * Hqz];                      // [B][S][512]
__device__ float g_encd[NDOC * 2 * Hdz];                    // [B][S][D][512]
__device__ float g_sessH[Bz * Hsz], g_sessC[Bz * Hsz];
__device__ float g_histH[Sz * Bz * Hsz], g_histC[Sz * Bz * Hsz];
__device__ float g_comb[Bz * Hsz];
__device__ float g_sgates[Bz * 4 * Hsz];
__device__ float g_decH[NDEC * Hsz], g_decC[NDEC * Hsz];

__device__ int g_qTok[QLz * QLANES];
__device__ int g_dTok[DLz * DLANES];
__device__ int g_decTok[TDEC * NDEC];
__device__ int g_decTgt[TDEC * NDEC];

__device__ float g_click, g_dloss, g_dcnt;

// ---------------- helpers ----------------
__device__ __forceinline__ float sigf(float x) { return 1.0f / (1.0f + expf(-x)); }

// ---------------- generic tiled NT GEMM ----------------
// C[M][N] (+)= Arow(r) . Wrow(n)  (+ bias[n])
// Arow(r): if tok != null -> emb + tok[r]*K (K contiguous), else A + r*lda
// W/bias selected per row-tile: dir = ((row0 % lanes) < halfLanes) ? 0 : 1
// Requires: N % 64 == 0, K % 16 == 0, halfLanes % 64 == 0 (or single weight set).
__global__ __launch_bounds__(256) void gemm_nt(
    const float* __restrict__ A, int lda,
    const int* __restrict__ tok,
    const float* __restrict__ emb,
    const float* __restrict__ W0, const float* __restrict__ W1, int ldw,
    const float* __restrict__ b0, const float* __restrict__ b1,
    float* __restrict__ C, int ldc,
    int M, int N, int K,
    int lanes, int halfLanes, int accumulate)
{
    __shared__ float As[16][65];
    __shared__ float Ws[16][65];

    const int tid  = threadIdx.x;          // 0..255
    const int row0 = blockIdx.y * 64;
    const int col0 = blockIdx.x * 64;

    const int dir = ((row0 % lanes) < halfLanes) ? 0 : 1;
    const float* W    = dir ? W1 : W0;
    const float* bias = dir ? b1 : b0;

    const int lr = tid >> 2;               // 0..63
    const int lk = (tid & 3) << 2;         // 0,4,8,12

    const int ty4 = (tid >> 4) << 2;       // row within tile (x4)
    const int tx4 = (tid & 15) << 2;       // col within tile (x4)

    float acc[4][4];
#pragma unroll
    for (int i = 0; i < 4; i++)
#pragma unroll
        for (int j = 0; j < 4; j++) acc[i][j] = 0.0f;

    // resolve A row pointer for this thread's load row
    const int ar = row0 + lr;
    const float* arow;
    if (tok) {
        int r = (ar < M) ? ar : 0;
        arow = emb + (size_t)tok[r] * K;
    } else {
        arow = A + (size_t)((ar < M) ? ar : 0) * lda;
    }
    const float* wrow = W + (size_t)(col0 + lr) * ldw;
    const bool arow_ok = (ar < M);

    for (int k0 = 0; k0 < K; k0 += 16) {
        float4 av = *(const float4*)(arow + k0 + lk);
        if (!arow_ok) av = make_float4(0.f, 0.f, 0.f, 0.f);
        float4 wv = *(const float4*)(wrow + k0 + lk);
        As[lk + 0][lr] = av.x; As[lk + 1][lr] = av.y;
        As[lk + 2][lr] = av.z; As[lk + 3][lr] = av.w;
        Ws[lk + 0][lr] = wv.x; Ws[lk + 1][lr] = wv.y;
        Ws[lk + 2][lr] = wv.z; Ws[lk + 3][lr] = wv.w;
        __syncthreads();
#pragma unroll
        for (int k = 0; k < 16; k++) {
            float a0 = As[k][ty4 + 0], a1 = As[k][ty4 + 1];
            float a2 = As[k][ty4 + 2], a3 = As[k][ty4 + 3];
            float w0 = Ws[k][tx4 + 0], w1 = Ws[k][tx4 + 1];
            float w2 = Ws[k][tx4 + 2], w3 = Ws[k][tx4 + 3];
            acc[0][0] += a0 * w0; acc[0][1] += a0 * w1; acc[0][2] += a0 * w2; acc[0][3] += a0 * w3;
            acc[1][0] += a1 * w0; acc[1][1] += a1 * w1; acc[1][2] += a1 * w2; acc[1][3] += a1 * w3;
            acc[2][0] += a2 * w0; acc[2][1] += a2 * w1; acc[2][2] += a2 * w2; acc[2][3] += a2 * w3;
            acc[3][0] += a3 * w0; acc[3][1] += a3 * w1; acc[3][2] += a3 * w2; acc[3][3] += a3 * w3;
        }
        __syncthreads();
    }

#pragma unroll
    for (int i = 0; i < 4; i++) {
        int r = row0 + ty4 + i;
        if (r >= M) continue;
        float* cp = C + (size_t)r * ldc + col0 + tx4;
#pragma unroll
        for (int j = 0; j < 4; j++) {
            float v = acc[i][j];
            if (accumulate) cp[j] += v;
            else            cp[j]  = v + (bias ? bias[col0 + tx4 + j] : 0.0f);
        }
    }
}

// ---------------- init / fill ----------------
__global__ void k_fill(float* p, int n, float v) {
    int i = blockIdx.x * blockDim.x + threadIdx.x;
    if (i < n) p[i] = v;
}
__global__ void k_zero_scal() { g_click = 0.f; g_dloss = 0.f; g_dcnt = 0.f; }

// ---------------- token tables ----------------
__global__ void k_qtok(const int* __restrict__ sq) {
    int i = blockIdx.x * blockDim.x + threadIdx.x;
    if (i >= QLz * QLANES) return;
    int t = i / QLANES, lane = i % QLANES;
    int n  = (lane < NQ) ? lane : lane - NQ;
    int tt = (lane < NQ) ? t : (QLz - 1 - t);
    g_qTok[i] = sq[n * QLz + tt];
}
__global__ void k_dtok(const int* __restrict__ rd) {
    int i = blockIdx.x * blockDim.x + threadIdx.x;
    if (i >= DLz * DLANES) return;
    int t = i / DLANES, lane = i % DLANES;
    int n  = (lane < NDOC) ? lane : lane - NDOC;
    int tt = (lane < NDOC) ? t : (DLz - 1 - t);
    g_dTok[i] = rd[n * DLz + tt];
}
__global__ void k_dectok(const int* __restrict__ sq) {
    int i = blockIdx.x * blockDim.x + threadIdx.x;
    if (i >= TDEC * NDEC) return;
    int t = i / NDEC, n = i % NDEC;
    int b = n / (Sz - 1), s = n % (Sz - 1);
    const int* qrow = sq + (b * Sz + s + 1) * QLz;
    g_decTok[i] = qrow[t];
    g_decTgt[i] = qrow[t + 1];
}

// ---------------- encoder step (gates already = xW + b + hU) ----------------
__global__ void k_enc_step(const float* __restrict__ gates,
                           float* __restrict__ h, float* __restrict__ c,
                           float* __restrict__ rmax,
                           const int* __restrict__ lens,
                           int lanes, int half, int H, int T, int t)
{
    int idx = blockIdx.x * blockDim.x + threadIdx.x;
    if (idx >= lanes * H) return;
    int lane = idx / H, j = idx % H;
    int n = (lane < half) ? lane : lane - half;
    int len = lens[n];
    bool valid = (lane < half) ? (t < len) : (t >= T - len);
    if (!valid) return;
    const float* g = gates + (size_t)lane * 4 * H;
    float gi = g[j], gf = g[H + j], gg = g[2 * H + j], go = g[3 * H + j];
    float cn = sigf(gf) * c[idx] + sigf(gi) * tanhf(gg);
    float hn = sigf(go) * tanhf(cn);
    c[idx] = cn; h[idx] = hn;
    float r = rmax[idx];
    rmax[idx] = (hn > r) ? hn : r;
}

// ---------------- encoder output assembly ----------------
__global__ void k_build_encq() {
    int i = blockIdx.x * blockDim.x + threadIdx.x;
    if (i >= NQ * 2 * Hqz) return;
    int n = i / (2 * Hqz), j = i % (2 * Hqz);
    g_encq[i] = (j < Hqz) ? g_qrmax[n * Hqz + j]
                          : g_qrmax[(NQ + n) * Hqz + (j - Hqz)];
}
__global__ void k_build_encd() {
    int i = blockIdx.x * blockDim.x + threadIdx.x;
    if (i >= NDOC * 2 * Hdz) return;
    int n = i / (2 * Hdz), j = i % (2 * Hdz);
    g_encd[i] = (j < Hdz) ? g_drmax[n * Hdz + j]
                          : g_drmax[(NDOC + n) * Hdz + (j - Hdz)];
}

// ---------------- block reductions ----------------
__device__ __forceinline__ float blockReduceSum256(float v, float* sh) {
#pragma unroll
    for (int o = 16; o > 0; o >>= 1) v += __shfl_down_sync(0xffffffff, v, o);
    int lane = threadIdx.x & 31, w = threadIdx.x >> 5;
    if (lane == 0) sh[w] = v;
    __syncthreads();
    v = (threadIdx.x < 8) ? sh[threadIdx.x] : 0.f;
    if (w == 0) {
#pragma unroll
        for (int o = 4; o > 0; o >>= 1) v += __shfl_down_sync(0xffffffff, v, o);
    }
    __syncthreads();
    return v;  // valid on thread 0
}
__device__ __forceinline__ float blockReduceMax256(float v, float* sh) {
#pragma unroll
    for (int o = 16; o > 0; o >>= 1) v = fmaxf(v, __shfl_down_sync(0xffffffff, v, o));
    int lane = threadIdx.x & 31, w = threadIdx.x >> 5;
    if (lane == 0) sh[w] = v;
    __syncthreads();
    v = (threadIdx.x < 8) ? sh[threadIdx.x] : NEGF;
    if (w == 0) {
#pragma unroll
        for (int o = 4; o > 0; o >>= 1) v = fmaxf(v, __shfl_down_sync(0xffffffff, v, o));
    }
    __syncthreads();
    return v;  // valid on thread 0
}

// ---------------- session: tanh + scores + BCE ----------------
__global__ void k_score_bce(const float* __restrict__ labels, int s) {
    __shared__ float comb[Hsz];
    __shared__ float red[8];
    int b = blockIdx.x;
    for (int j = threadIdx.x; j < Hsz; j += blockDim.x)
        comb[j] = tanhf(g_comb[b * Hsz + j]);
    __syncthreads();
    float local = 0.f;
    for (int d = 0; d < Dz; d++) {
        const float* ed = g_encd + (size_t)(((b * Sz + s) * Dz + d)) * (2 * Hdz);
        float p = 0.f;
        for (int j = threadIdx.x; j < 2 * Hdz; j += blockDim.x)
            p += comb[j] * ed[j];
        float score = blockReduceSum256(p, red);
        if (threadIdx.x == 0) {
            float lab = labels[(b * Sz + s) * Dz + d];
            local += fmaxf(score, 0.f) - score * lab + log1pf(expf(-fabsf(score)));
        }
    }
    if (threadIdx.x == 0) atomicAdd(&g_click, local);
}

// ---------------- session LSTM cell ----------------
__global__ void k_sess_cell(int s) {
    int idx = blockIdx.x * blockDim.x + threadIdx.x;
    if (idx >= Bz * Hsz) return;
    int b = idx / Hsz, j = idx % Hsz;
    const float* g = g_sgates + (size_t)b * 4 * Hsz;
    float gi = g[j], gf = g[Hsz + j], gg = g[2 * Hsz + j], go = g[3 * Hsz + j];
    float cn = sigf(gf) * g_sessC[idx] + sigf(gi) * tanhf(gg);
    float hn = sigf(go) * tanhf(cn);
    g_sessH[idx] = hn; g_sessC[idx] = cn;
    g_histH[s * Bz * Hsz + idx] = hn;
    g_histC[s * Bz * Hsz + idx] = cn;
}

// ---------------- decoder init / cell ----------------
__global__ void k_dec_init() {
    int idx = blockIdx.x * blockDim.x + threadIdx.x;
    if (idx >= NDEC * Hsz) return;
    int n = idx / Hsz, j = idx % Hsz;
    int b = n / (Sz - 1), s = n % (Sz - 1);
    g_decH[idx] = g_histH[(s * Bz + b) * Hsz + j];
    g_decC[idx] = g_histC[(s * Bz + b) * Hsz + j];
}
__global__ void k_dec_cell(const float* __restrict__ gates) {
    int idx = blockIdx.x * blockDim.x + threadIdx.x;
    if (idx >= NDEC * Hsz) return;
    int n = idx / Hsz, j = idx % Hsz;
    const float* g = gates + (size_t)n * 4 * Hsz;
    float gi = g[j], gf = g[Hsz + j], gg = g[2 * Hsz + j], go = g[3 * Hsz + j];
    float cn = sigf(gf) * g_decC[idx] + sigf(gi) * tanhf(gg);
    float hn = sigf(go) * tanhf(cn);
    g_decH[idx] = hn; g_decC[idx] = cn;
}

// ---------------- decoder NLL (2-pass logsumexp) ----------------
__global__ void k_nll(const int* __restrict__ sql, int t) {
    __shared__ float red[8];
    __shared__ float s_mx, s_sum;
    int n = blockIdx.x;
    int b = n / (Sz - 1), s = n % (Sz - 1);
    int len = sql[b * Sz + s + 1];
    if (t >= len) return;  // masked out
    const float* row = g_logits + (size_t)n * Vz;
    float mx = NEGF;
    for (int j = threadIdx.x; j < Vz; j += blockDim.x)
        mx = fmaxf(mx, row[j]);
    mx = blockReduceMax256(mx, red);
    if (threadIdx.x == 0) s_mx = mx;
    __syncthreads();
    mx = s_mx;
    float sum = 0.f;
    for (int j = threadIdx.x; j < Vz; j += blockDim.x)
        sum += expf(row[j] - mx);
    sum = blockReduceSum256(sum, red);
    if (threadIdx.x == 0) {
        float lse = mx + logf(sum);
        int tgt = g_decTgt[t * NDEC + n];
        float nll = lse - row[tgt];
        atomicAdd(&g_dloss, nll);
        atomicAdd(&g_dcnt, 1.0f);
    }
    (void)s_sum;
}

__global__ void k_final(float* out) {
    float dec = (g_dcnt > 0.f) ? (g_dloss / g_dcnt) : 0.f;
    out[0] = g_click / (float)(Bz * Dz * Sz) + dec;
}

// ---------------- host side ----------------
static inline void launch_gemm(const float* A, int lda, const int* tok, const float* emb,
                               const float* W0, const float* W1, int ldw,
                               const float* b0, const float* b1,
                               float* C, int ldc, int M, int N, int K,
                               int lanes, int half, int acc)
{
    dim3 grid(N / 64, (M + 63) / 64);
    gemm_nt<<<grid, 256>>>(A, lda, tok, emb, W0, W1, ldw, b0, b1,
                           C, ldc, M, N, K, lanes, half, acc);
}

#define GETSYM(var, sym) do { void* p_; cudaGetSymbolAddress(&p_, sym); var = (decltype(var))p_; } while (0)

extern "C" void kernel_launch(void* const* d_in, const int* in_sizes, int n_in,
                              void* d_out, int out_size)
{
    (void)in_sizes; (void)n_in; (void)out_size;
    const int*   sq     = (const int*)d_in[0];
    const int*   sql    = (const int*)d_in[1];
    const int*   rd     = (const int*)d_in[2];
    const int*   rdl    = (const int*)d_in[3];
    const float* labels = (const float*)d_in[4];
    const float* emb    = (const float*)d_in[5];
    const float* qWihf  = (const float*)d_in[6];
    const float* qWhhf  = (const float*)d_in[7];
    const float* qbf    = (const float*)d_in[8];
    const float* qWihb  = (const float*)d_in[9];
    const float* qWhhb  = (const float*)d_in[10];
    const float* qbb    = (const float*)d_in[11];
    const float* dWihf  = (const float*)d_in[12];
    const float* dWhhf  = (const float*)d_in[13];
    const float* dbf    = (const float*)d_in[14];
    const float* dWihb  = (const float*)d_in[15];
    const float* dWhhb  = (const float*)d_in[16];
    const float* dbb    = (const float*)d_in[17];
    const float* sWih   = (const float*)d_in[18];
    const float* sWhh   = (const float*)d_in[19];
    const float* sb     = (const float*)d_in[20];
    const float* projW  = (const float*)d_in[21];
    const float* projb  = (const float*)d_in[22];
    const float* decWih = (const float*)d_in[23];
    const float* decWhh = (const float*)d_in[24];
    const float* decb   = (const float*)d_in[25];
    const float* outW   = (const float*)d_in[26];
    const float* outb   = (const float*)d_in[27];

    float *qGates, *dGates, *decGates, *logits;
    float *qh, *qc, *qrmax, *dh, *dc, *drmax, *encq, *sessH;
    int *qTok, *dTok;
    GETSYM(qGates, g_qGates);   GETSYM(dGates, g_dGates);
    GETSYM(decGates, g_decGates); GETSYM(logits, g_logits);
    GETSYM(qh, g_qh); GETSYM(qc, g_qc); GETSYM(qrmax, g_qrmax);
    GETSYM(dh, g_dh); GETSYM(dc, g_dc); GETSYM(drmax, g_drmax);
    GETSYM(encq, g_encq); GETSYM(sessH, g_sessH);
    GETSYM(qTok, g_qTok); GETSYM(dTok, g_dTok);
    int *decTok; GETSYM(decTok, g_decTok);
    float *decH; GETSYM(decH, g_decH);

    const int TPB = 256;
    // ---- init state ----
    k_fill<<<(QLANES * Hqz + TPB - 1) / TPB, TPB>>>(qh, QLANES * Hqz, 0.f);
    k_fill<<<(QLANES * Hqz + TPB - 1) / TPB, TPB>>>(qc, QLANES * Hqz, 0.f);
    k_fill<<<(QLANES * Hqz + TPB - 1) / TPB, TPB>>>(qrmax, QLANES * Hqz, NEGF);
    k_fill<<<(DLANES * Hdz + TPB - 1) / TPB, TPB>>>(dh, DLANES * Hdz, 0.f);
    k_fill<<<(DLANES * Hdz + TPB - 1) / TPB, TPB>>>(dc, DLANES * Hdz, 0.f);
    k_fill<<<(DLANES * Hdz + TPB - 1) / TPB, TPB>>>(drmax, DLANES * Hdz, NEGF);
    k_fill<<<(Bz * Hsz + TPB - 1) / TPB, TPB>>>(sessH, Bz * Hsz, 0.f);
    {
        float* sessC; GETSYM(sessC, g_sessC);
        k_fill<<<(Bz * Hsz + TPB - 1) / TPB, TPB>>>(sessC, Bz * Hsz, 0.f);
    }
    k_zero_scal<<<1, 1>>>();

    // ---- token tables ----
    k_qtok<<<(QLz * QLANES + TPB - 1) / TPB, TPB>>>(sq);
    k_dtok<<<(DLz * DLANES + TPB - 1) / TPB, TPB>>>(rd);
    k_dectok<<<(TDEC * NDEC + TPB - 1) / TPB, TPB>>>(sq);

    // ---- x-part gate precompute (gather GEMMs) ----
    launch_gemm(nullptr, 0, qTok, emb, qWihf, qWihb, Ez, qbf, qbb,
                qGates, 4 * Hqz, QLz * QLANES, 4 * Hqz, Ez, QLANES, NQ, 0);
    launch_gemm(nullptr, 0, dTok, emb, dWihf, dWihb, Ez, dbf, dbb,
                dGates, 4 * Hdz, DLz * DLANES, 4 * Hdz, Ez, DLANES, NDOC, 0);
    launch_gemm(nullptr, 0, decTok, emb, decWih, decWih, Ez, decb, decb,
                decGates, 4 * Hsz, TDEC * NDEC, 4 * Hsz, Ez, TDEC * NDEC, TDEC * NDEC, 0);

    // ---- query BiLSTM ----
    for (int t = 0; t < QLz; t++) {
        float* gt = qGates + (size_t)t * QLANES * 4 * Hqz;
        launch_gemm(qh, Hqz, nullptr, nullptr, qWhhf, qWhhb, Hqz, nullptr, nullptr,
                    gt, 4 * Hqz, QLANES, 4 * Hqz, Hqz, QLANES, NQ, 1);
        k_enc_step<<<(QLANES * Hqz + TPB - 1) / TPB, TPB>>>(gt, qh, qc, qrmax,
                                                            sql, QLANES, NQ, Hqz, QLz, t);
    }

    // ---- doc BiLSTM ----
    for (int t = 0; t < DLz; t++) {
        float* gt = dGates + (size_t)t * DLANES * 4 * Hdz;
        launch_gemm(dh, Hdz, nullptr, nullptr, dWhhf, dWhhb, Hdz, nullptr, nullptr,
                    gt, 4 * Hdz, DLANES, 4 * Hdz, Hdz, DLANES, NDOC, 1);
        k_enc_step<<<(DLANES * Hdz + TPB - 1) / TPB, TPB>>>(gt, dh, dc, drmax,
                                                            rdl, DLANES, NDOC, Hdz, DLz, t);
    }

    // ---- assemble encoder outputs ----
    k_build_encq<<<(NQ * 2 * Hqz + TPB - 1) / TPB, TPB>>>();
    k_build_encd<<<(NDOC * 2 * Hdz + TPB - 1) / TPB, TPB>>>();

    // ---- session loop ----
    float* comb;   GETSYM(comb, g_comb);
    float* sgates; GETSYM(sgates, g_sgates);
    for (int s = 0; s < Sz; s++) {
        // comb_pre = eq_s @ projW[:, :512]^T + h @ projW[:, 512:]^T + projb
        launch_gemm(encq + s * (2 * Hqz), Sz * 2 * Hqz, nullptr, nullptr,
                    projW, projW, 2 * Hqz + Hsz, projb, projb,
                    comb, Hsz, Bz, Hsz, 2 * Hqz, Bz, Bz, 0);
        launch_gemm(sessH, Hsz, nullptr, nullptr,
                    projW + 2 * Hqz, projW + 2 * Hqz, 2 * Hqz + Hsz, nullptr, nullptr,
                    comb, Hsz, Bz, Hsz, Hsz, Bz, Bz, 1);
        k_score_bce<<<Bz, 256>>>(labels, s);
        // session LSTM gates
        launch_gemm(encq + s * (2 * Hqz), Sz * 2 * Hqz, nullptr, nullptr,
                    sWih, sWih, 2 * Hqz, sb, sb,
                    sgates, 4 * Hsz, Bz, 4 * Hsz, 2 * Hqz, Bz, Bz, 0);
        launch_gemm(sessH, Hsz, nullptr, nullptr, sWhh, sWhh, Hsz, nullptr, nullptr,
                    sgates, 4 * Hsz, Bz, 4 * Hsz, Hsz, Bz, Bz, 1);
        k_sess_cell<<<(Bz * Hsz + TPB - 1) / TPB, TPB>>>(s);
    }

    // ---- decoder ----
    k_dec_init<<<(NDEC * Hsz + TPB - 1) / TPB, TPB>>>();
    for (int t = 0; t < TDEC; t++) {
        float* gt = decGates + (size_t)t * NDEC * 4 * Hsz;
        launch_gemm(decH, Hsz, nullptr, nullptr, decWhh, decWhh, Hsz, nullptr, nullptr,
                    gt, 4 * Hsz, NDEC, 4 * Hsz, Hsz, NDEC, NDEC, 1);
        k_dec_cell<<<(NDEC * Hsz + TPB - 1) / TPB, TPB>>>(gt);
        launch_gemm(decH, Hsz, nullptr, nullptr, outW, outW, Hsz, outb, outb,
                    logits, Vz, NDEC, Vz, Hsz, NDEC, NDEC, 0);
        k_nll<<<NDEC, 256>>>(sql, t);
    }

    k_final<<<1, 1>>>((float*)d_out);
}

// round 3
// speedup vs baseline: 1.5062x; 1.5062x over previous
#include <cuda_runtime.h>
#include <math.h>
#include <stdint.h>

// ---------------- problem constants ----------------
#define Bz   32
#define Sz   4
#define QLz  12
#define Dz   10
#define DLz  40
#define Vz   32000
#define Ez   256
#define Hqz  256
#define Hdz  256
#define Hsz  512

#define NQ     128            // B*S query sequences
#define NDOC   1280           // B*S*D doc sequences
#define QLANES 256            // fwd+bwd
#define DLANES 2560
#define NDEC   96             // B*(S-1)
#define TDEC   11             // QL-1
#define NEGF   (-1000000000.0f)

// ---------------- scratch (device globals) ------------
__device__ float g_qGates[QLz * QLANES * 4 * Hqz];
__device__ float g_dGates[DLz * DLANES * 4 * Hdz];          // 419MB
__device__ float g_decGates[TDEC * NDEC * 4 * Hsz];
__device__ float g_logits[NDEC * Vz];

__device__ float g_qh[QLANES * Hqz], g_qc[QLANES * Hqz], g_qrmax[QLANES * Hqz];
__device__ float g_dh[DLANES * Hdz], g_dc[DLANES * Hdz], g_drmax[DLANES * Hdz];
__device__ float g_encq[NQ * 2 * Hqz];
__device__ float g_encd[NDOC * 2 * Hdz];
__device__ float g_sessH[Bz * Hsz], g_sessC[Bz * Hsz];
__device__ float g_histH[Sz * Bz * Hsz], g_histC[Sz * Bz * Hsz];
__device__ float g_comb[Bz * Hsz];
__device__ float g_sgates[Bz * 4 * Hsz];
__device__ float g_decH[NDEC * Hsz], g_decC[NDEC * Hsz];

__device__ int g_qTok[QLz * QLANES];
__device__ int g_dTok[DLz * DLANES];
__device__ int g_decTok[TDEC * NDEC];
__device__ int g_decTgt[TDEC * NDEC];

// doc length-sort data
__device__ int g_permD[NDOC];    // sorted lane -> doc
__device__ int g_ilaneD[NDOC];   // doc -> sorted lane
__device__ int g_slenD[NDOC];    // sorted lengths (descending)
__device__ int g_cntF[DLz];      // #{len > t}
__device__ int g_cntB[DLz];      // #{len >= DLz - t}

__device__ float g_click, g_dloss, g_dcnt;

// ---------------- helpers ----------------
__device__ __forceinline__ float sigf(float x) { return 1.0f / (1.0f + expf(-x)); }

// =======================================================================
// BIG GEMM: 128x128 tile, 256 threads, 8x8 per thread, fp32
// C[M][N] (+)= Arow(r) . Wrow(n) (+ bias). tok!=null -> A row = emb[tok[r]].
// Dual weights by lane half (row-tile granularity; requires lanes,half %128==0
// when dual). Optional per-t active-count skip (cntF/cntB, t = row0/lanes).
// Requires N%128==0, K%16==0.
// =======================================================================
__global__ __launch_bounds__(256) void gemm_nt_big(
    const float* __restrict__ A, int lda,
    const int* __restrict__ tok,
    const float* __restrict__ emb,
    const float* __restrict__ W0, const float* __restrict__ W1, int ldw,
    const float* __restrict__ b0, const float* __restrict__ b1,
    float* __restrict__ C, int ldc,
    int M, int N, int K,
    int lanes, int halfLanes, int accumulate,
    const int* __restrict__ cntF, const int* __restrict__ cntB)
{
    const int row0 = blockIdx.y * 128;
    const int col0 = blockIdx.x * 128;

    const int lane0 = row0 % lanes;
    if (cntF) {
        const int t = row0 / lanes;
        if (lane0 < halfLanes) { if (lane0 >= cntF[t]) return; }
        else                   { if (lane0 - halfLanes >= cntB[t]) return; }
    }
    const int dir = (lane0 < halfLanes) ? 0 : 1;
    const float* W    = dir ? W1 : W0;
    const float* bias = dir ? b1 : b0;

    __shared__ float As[16][128];
    __shared__ float Ws[16][128];

    const int tid = threadIdx.x;
    const int tx = tid & 15;          // 0..15
    const int ty = tid >> 4;          // 0..15

    // loader mapping: one row per 2 threads, 8 k-floats per thread
    const int lr = tid >> 1;          // 0..127
    const int lk = (tid & 1) << 3;    // 0 or 8

    const int ar = row0 + lr;
    const bool aok = (ar < M);
    const float* arow;
    if (tok) arow = emb + (size_t)tok[aok ? ar : 0] * K;
    else     arow = A + (size_t)(aok ? ar : 0) * lda;
    const float* wrow = W + (size_t)(col0 + lr) * ldw;

    float acc[8][8];
#pragma unroll
    for (int i = 0; i < 8; i++)
#pragma unroll
        for (int j = 0; j < 8; j++) acc[i][j] = 0.0f;

    float4 av0, av1, wv0, wv1;
    // prologue load chunk 0
    {
        av0 = aok ? *(const float4*)(arow + lk)     : make_float4(0,0,0,0);
        av1 = aok ? *(const float4*)(arow + lk + 4) : make_float4(0,0,0,0);
        wv0 = *(const float4*)(wrow + lk);
        wv1 = *(const float4*)(wrow + lk + 4);
        As[lk+0][lr]=av0.x; As[lk+1][lr]=av0.y; As[lk+2][lr]=av0.z; As[lk+3][lr]=av0.w;
        As[lk+4][lr]=av1.x; As[lk+5][lr]=av1.y; As[lk+6][lr]=av1.z; As[lk+7][lr]=av1.w;
        Ws[lk+0][lr]=wv0.x; Ws[lk+1][lr]=wv0.y; Ws[lk+2][lr]=wv0.z; Ws[lk+3][lr]=wv0.w;
        Ws[lk+4][lr]=wv1.x; Ws[lk+5][lr]=wv1.y; Ws[lk+6][lr]=wv1.z; Ws[lk+7][lr]=wv1.w;
    }
    __syncthreads();

    for (int k0 = 0; k0 < K; k0 += 16) {
        const bool more = (k0 + 16) < K;
        if (more) {
            const int kn = k0 + 16 + lk;
            av0 = aok ? *(const float4*)(arow + kn)     : make_float4(0,0,0,0);
            av1 = aok ? *(const float4*)(arow + kn + 4) : make_float4(0,0,0,0);
            wv0 = *(const float4*)(wrow + kn);
            wv1 = *(const float4*)(wrow + kn + 4);
        }
#pragma unroll
        for (int k = 0; k < 16; k++) {
            float a[8], w[8];
            float4 t0 = *(const float4*)&As[k][ty*4];
            float4 t1 = *(const float4*)&As[k][64 + ty*4];
            float4 u0 = *(const float4*)&Ws[k][tx*4];
            float4 u1 = *(const float4*)&Ws[k][64 + tx*4];
            a[0]=t0.x; a[1]=t0.y; a[2]=t0.z; a[3]=t0.w;
            a[4]=t1.x; a[5]=t1.y; a[6]=t1.z; a[7]=t1.w;
            w[0]=u0.x; w[1]=u0.y; w[2]=u0.z; w[3]=u0.w;
            w[4]=u1.x; w[5]=u1.y; w[6]=u1.z; w[7]=u1.w;
#pragma unroll
            for (int i = 0; i < 8; i++)
#pragma unroll
                for (int j = 0; j < 8; j++)
                    acc[i][j] += a[i] * w[j];
        }
        __syncthreads();
        if (more) {
            As[lk+0][lr]=av0.x; As[lk+1][lr]=av0.y; As[lk+2][lr]=av0.z; As[lk+3][lr]=av0.w;
            As[lk+4][lr]=av1.x; As[lk+5][lr]=av1.y; As[lk+6][lr]=av1.z; As[lk+7][lr]=av1.w;
            Ws[lk+0][lr]=wv0.x; Ws[lk+1][lr]=wv0.y; Ws[lk+2][lr]=wv0.z; Ws[lk+3][lr]=wv0.w;
            Ws[lk+4][lr]=wv1.x; Ws[lk+5][lr]=wv1.y; Ws[lk+6][lr]=wv1.z; Ws[lk+7][lr]=wv1.w;
            __syncthreads();
        }
    }

    // epilogue
#pragma unroll
    for (int ih = 0; ih < 2; ih++) {
#pragma unroll
        for (int i = 0; i < 4; i++) {
            const int r = row0 + ih*64 + ty*4 + i;
            if (r >= M) continue;
            float* cp = C + (size_t)r * ldc + col0;
#pragma unroll
            for (int jh = 0; jh < 2; jh++) {
                const int c = jh*64 + tx*4;
                float4 v;
                v.x = acc[ih*4+i][jh*4+0];
                v.y = acc[ih*4+i][jh*4+1];
                v.z = acc[ih*4+i][jh*4+2];
                v.w = acc[ih*4+i][jh*4+3];
                if (accumulate) {
                    float4 o = *(const float4*)(cp + c);
                    v.x += o.x; v.y += o.y; v.z += o.z; v.w += o.w;
                } else if (bias) {
                    float4 o = *(const float4*)(bias + col0 + c);
                    v.x += o.x; v.y += o.y; v.z += o.z; v.w += o.w;
                }
                *(float4*)(cp + c) = v;
            }
        }
    }
}

// =======================================================================
// SMALL GEMM: 64x64 tile for small M/N
// =======================================================================
__global__ __launch_bounds__(256) void gemm_nt(
    const float* __restrict__ A, int lda,
    const int* __restrict__ tok,
    const float* __restrict__ emb,
    const float* __restrict__ W0, const float* __restrict__ W1, int ldw,
    const float* __restrict__ b0, const float* __restrict__ b1,
    float* __restrict__ C, int ldc,
    int M, int N, int K,
    int lanes, int halfLanes, int accumulate)
{
    __shared__ float As[16][65];
    __shared__ float Ws[16][65];

    const int tid  = threadIdx.x;
    const int row0 = blockIdx.y * 64;
    const int col0 = blockIdx.x * 64;

    const int dir = ((row0 % lanes) < halfLanes) ? 0 : 1;
    const float* W    = dir ? W1 : W0;
    const float* bias = dir ? b1 : b0;

    const int lr = tid >> 2;
    const int lk = (tid & 3) << 2;
    const int ty4 = (tid >> 4) << 2;
    const int tx4 = (tid & 15) << 2;

    float acc[4][4];
#pragma unroll
    for (int i = 0; i < 4; i++)
#pragma unroll
        for (int j = 0; j < 4; j++) acc[i][j] = 0.0f;

    const int ar = row0 + lr;
    const float* arow;
    if (tok) arow = emb + (size_t)tok[(ar < M) ? ar : 0] * K;
    else     arow = A + (size_t)((ar < M) ? ar : 0) * lda;
    const float* wrow = W + (size_t)(col0 + lr) * ldw;
    const bool arow_ok = (ar < M);

    for (int k0 = 0; k0 < K; k0 += 16) {
        float4 av = *(const float4*)(arow + k0 + lk);
        if (!arow_ok) av = make_float4(0.f, 0.f, 0.f, 0.f);
        float4 wv = *(const float4*)(wrow + k0 + lk);
        As[lk + 0][lr] = av.x; As[lk + 1][lr] = av.y;
        As[lk + 2][lr] = av.z; As[lk + 3][lr] = av.w;
        Ws[lk + 0][lr] = wv.x; Ws[lk + 1][lr] = wv.y;
        Ws[lk + 2][lr] = wv.z; Ws[lk + 3][lr] = wv.w;
        __syncthreads();
#pragma unroll
        for (int k = 0; k < 16; k++) {
            float a0 = As[k][ty4 + 0], a1 = As[k][ty4 + 1];
            float a2 = As[k][ty4 + 2], a3 = As[k][ty4 + 3];
            float w0 = Ws[k][tx4 + 0], w1 = Ws[k][tx4 + 1];
            float w2 = Ws[k][tx4 + 2], w3 = Ws[k][tx4 + 3];
            acc[0][0] += a0 * w0; acc[0][1] += a0 * w1; acc[0][2] += a0 * w2; acc[0][3] += a0 * w3;
            acc[1][0] += a1 * w0; acc[1][1] += a1 * w1; acc[1][2] += a1 * w2; acc[1][3] += a1 * w3;
            acc[2][0] += a2 * w0; acc[2][1] += a2 * w1; acc[2][2] += a2 * w2; acc[2][3] += a2 * w3;
            acc[3][0] += a3 * w0; acc[3][1] += a3 * w1; acc[3][2] += a3 * w2; acc[3][3] += a3 * w3;
        }
        __syncthreads();
    }

#pragma unroll
    for (int i = 0; i < 4; i++) {
        int r = row0 + ty4 + i;
        if (r >= M) continue;
        float* cp = C + (size_t)r * ldc + col0 + tx4;
#pragma unroll
        for (int j = 0; j < 4; j++) {
            float v = acc[i][j];
            if (accumulate) cp[j] += v;
            else            cp[j]  = v + (bias ? bias[col0 + tx4 + j] : 0.0f);
        }
    }
}

// ---------------- init / fill ----------------
__global__ void k_fill(float* p, int n, float v) {
    int i = blockIdx.x * blockDim.x + threadIdx.x;
    if (i < n) p[i] = v;
}
__global__ void k_zero_scal() { g_click = 0.f; g_dloss = 0.f; g_dcnt = 0.f; }

// ---------------- doc counting sort (descending by length) ----------------
__global__ void k_sortD(const int* __restrict__ rdl) {
    __shared__ int hist[DLz + 1];
    __shared__ int off[DLz + 1];
    int tid = threadIdx.x;
    for (int i = tid; i <= DLz; i += blockDim.x) hist[i] = 0;
    __syncthreads();
    for (int i = tid; i < NDOC; i += blockDim.x) atomicAdd(&hist[rdl[i]], 1);
    __syncthreads();
    if (tid == 0) {
        int acc = 0;
        for (int l = DLz; l >= 1; l--) { off[l] = acc; acc += hist[l]; }
    }
    __syncthreads();
    for (int t = tid; t < DLz; t += blockDim.x) {
        int cf = 0, cb = 0;
        for (int l = t + 1; l <= DLz; l++) cf += hist[l];
        for (int l = DLz - t; l <= DLz; l++) cb += hist[l];
        g_cntF[t] = cf;
        g_cntB[t] = cb;
    }
    __syncthreads();
    for (int i = tid; i < NDOC; i += blockDim.x) {
        int len = rdl[i];
        int pos = atomicAdd(&off[len], 1);
        g_permD[pos] = i;
        g_slenD[pos] = len;
        g_ilaneD[i] = pos;
    }
}

// ---------------- token tables ----------------
__global__ void k_qtok(const int* __restrict__ sq) {
    int i = blockIdx.x * blockDim.x + threadIdx.x;
    if (i >= QLz * QLANES) return;
    int t = i / QLANES, lane = i % QLANES;
    int n  = (lane < NQ) ? lane : lane - NQ;
    int tt = (lane < NQ) ? t : (QLz - 1 - t);
    g_qTok[i] = sq[n * QLz + tt];
}
__global__ void k_dtok(const int* __restrict__ rd) {
    int i = blockIdx.x * blockDim.x + threadIdx.x;
    if (i >= DLz * DLANES) return;
    int t = i / DLANES, lane = i % DLANES;
    int slane = (lane < NDOC) ? lane : lane - NDOC;
    int doc = g_permD[slane];
    int tt = (lane < NDOC) ? t : (DLz - 1 - t);
    g_dTok[i] = rd[doc * DLz + tt];
}
__global__ void k_dectok(const int* __restrict__ sq) {
    int i = blockIdx.x * blockDim.x + threadIdx.x;
    if (i >= TDEC * NDEC) return;
    int t = i / NDEC, n = i % NDEC;
    int b = n / (Sz - 1), s = n % (Sz - 1);
    const int* qrow = sq + (b * Sz + s + 1) * QLz;
    g_decTok[i] = qrow[t];
    g_decTgt[i] = qrow[t + 1];
}

// ---------------- encoder step ----------------
// lens indexed by (lane % half); for docs this is the SORTED lengths g_slenD.
__global__ void k_enc_step(const float* __restrict__ gates,
                           float* __restrict__ h, float* __restrict__ c,
                           float* __restrict__ rmax,
                           const int* __restrict__ lens,
                           int lanes, int half, int H, int T, int t)
{
    int idx = blockIdx.x * blockDim.x + threadIdx.x;
    if (idx >= lanes * H) return;
    int lane = idx / H, j = idx % H;
    int n = (lane < half) ? lane : lane - half;
    int len = lens[n];
    bool valid = (lane < half) ? (t < len) : (t >= T - len);
    if (!valid) return;
    const float* g = gates + (size_t)lane * 4 * H;
    float gi = g[j], gf = g[H + j], gg = g[2 * H + j], go = g[3 * H + j];
    float cn = sigf(gf) * c[idx] + sigf(gi) * tanhf(gg);
    float hn = sigf(go) * tanhf(cn);
    c[idx] = cn; h[idx] = hn;
    float r = rmax[idx];
    rmax[idx] = (hn > r) ? hn : r;
}

// ---------------- encoder output assembly ----------------
__global__ void k_build_encq() {
    int i = blockIdx.x * blockDim.x + threadIdx.x;
    if (i >= NQ * 2 * Hqz) return;
    int n = i / (2 * Hqz), j = i % (2 * Hqz);
    g_encq[i] = (j < Hqz) ? g_qrmax[n * Hqz + j]
                          : g_qrmax[(NQ + n) * Hqz + (j - Hqz)];
}
__global__ void k_build_encd() {
    int i = blockIdx.x * blockDim.x + threadIdx.x;
    if (i >= NDOC * 2 * Hdz) return;
    int n = i / (2 * Hdz), j = i % (2 * Hdz);
    int lane = g_ilaneD[n];
    g_encd[i] = (j < Hdz) ? g_drmax[lane * Hdz + j]
                          : g_drmax[(NDOC + lane) * Hdz + (j - Hdz)];
}

// ---------------- block reductions ----------------
__device__ __forceinline__ float blockReduceSum256(float v, float* sh) {
#pragma unroll
    for (int o = 16; o > 0; o >>= 1) v += __shfl_down_sync(0xffffffff, v, o);
    int lane = threadIdx.x & 31, w = threadIdx.x >> 5;
    if (lane == 0) sh[w] = v;
    __syncthreads();
    v = (threadIdx.x < 8) ? sh[threadIdx.x] : 0.f;
    if (w == 0) {
#pragma unroll
        for (int o = 4; o > 0; o >>= 1) v += __shfl_down_sync(0xffffffff, v, o);
    }
    __syncthreads();
    return v;
}
__device__ __forceinline__ float blockReduceMax256(float v, float* sh) {
#pragma unroll
    for (int o = 16; o > 0; o >>= 1) v = fmaxf(v, __shfl_down_sync(0xffffffff, v, o));
    int lane = threadIdx.x & 31, w = threadIdx.x >> 5;
    if (lane == 0) sh[w] = v;
    __syncthreads();
    v = (threadIdx.x < 8) ? sh[threadIdx.x] : NEGF;
    if (w == 0) {
#pragma unroll
        for (int o = 4; o > 0; o >>= 1) v = fmaxf(v, __shfl_down_sync(0xffffffff, v, o));
    }
    __syncthreads();
    return v;
}

// ---------------- session: tanh + scores + BCE ----------------
__global__ void k_score_bce(const float* __restrict__ labels, int s) {
    __shared__ float comb[Hsz];
    __shared__ float red[8];
    int b = blockIdx.x;
    for (int j = threadIdx.x; j < Hsz; j += blockDim.x)
        comb[j] = tanhf(g_comb[b * Hsz + j]);
    __syncthreads();
    float local = 0.f;
    for (int d = 0; d < Dz; d++) {
        const float* ed = g_encd + (size_t)(((b * Sz + s) * Dz + d)) * (2 * Hdz);
        float p = 0.f;
        for (int j = threadIdx.x; j < 2 * Hdz; j += blockDim.x)
            p += comb[j] * ed[j];
        float score = blockReduceSum256(p, red);
        if (threadIdx.x == 0) {
            float lab = labels[(b * Sz + s) * Dz + d];
            local += fmaxf(score, 0.f) - score * lab + log1pf(expf(-fabsf(score)));
        }
    }
    if (threadIdx.x == 0) atomicAdd(&g_click, local);
}

// ---------------- session LSTM cell ----------------
__global__ void k_sess_cell(int s) {
    int idx = blockIdx.x * blockDim.x + threadIdx.x;
    if (idx >= Bz * Hsz) return;
    int b = idx / Hsz, j = idx % Hsz;
    const float* g = g_sgates + (size_t)b * 4 * Hsz;
    float gi = g[j], gf = g[Hsz + j], gg = g[2 * Hsz + j], go = g[3 * Hsz + j];
    float cn = sigf(gf) * g_sessC[idx] + sigf(gi) * tanhf(gg);
    float hn = sigf(go) * tanhf(cn);
    g_sessH[idx] = hn; g_sessC[idx] = cn;
    g_histH[s * Bz * Hsz + idx] = hn;
    g_histC[s * Bz * Hsz + idx] = cn;
}

// ---------------- decoder init / cell ----------------
__global__ void k_dec_init() {
    int idx = blockIdx.x * blockDim.x + threadIdx.x;
    if (idx >= NDEC * Hsz) return;
    int n = idx / Hsz, j = idx % Hsz;
    int b = n / (Sz - 1), s = n % (Sz - 1);
    g_decH[idx] = g_histH[(s * Bz + b) * Hsz + j];
    g_decC[idx] = g_histC[(s * Bz + b) * Hsz + j];
}
__global__ void k_dec_cell(const float* __restrict__ gates) {
    int idx = blockIdx.x * blockDim.x + threadIdx.x;
    if (idx >= NDEC * Hsz) return;
    int n = idx / Hsz, j = idx % Hsz;
    const float* g = gates + (size_t)n * 4 * Hsz;
    float gi = g[j], gf = g[Hsz + j], gg = g[2 * Hsz + j], go = g[3 * Hsz + j];
    float cn = sigf(gf) * g_decC[idx] + sigf(gi) * tanhf(gg);
    float hn = sigf(go) * tanhf(cn);
    g_decH[idx] = hn; g_decC[idx] = cn;
}

// ---------------- decoder NLL (2-pass logsumexp) ----------------
__global__ void k_nll(const int* __restrict__ sql, int t) {
    __shared__ float red[8];
    __shared__ float s_mx;
    int n = blockIdx.x;
    int b = n / (Sz - 1), s = n % (Sz - 1);
    int len = sql[b * Sz + s + 1];
    if (t >= len) return;
    const float* row = g_logits + (size_t)n * Vz;
    float mx = NEGF;
    for (int j = threadIdx.x; j < Vz; j += blockDim.x)
        mx = fmaxf(mx, row[j]);
    mx = blockReduceMax256(mx, red);
    if (threadIdx.x == 0) s_mx = mx;
    __syncthreads();
    mx = s_mx;
    float sum = 0.f;
    for (int j = threadIdx.x; j < Vz; j += blockDim.x)
        sum += expf(row[j] - mx);
    sum = blockReduceSum256(sum, red);
    if (threadIdx.x == 0) {
        float lse = mx + logf(sum);
        int tgt = g_decTgt[t * NDEC + n];
        float nll = lse - row[tgt];
        atomicAdd(&g_dloss, nll);
        atomicAdd(&g_dcnt, 1.0f);
    }
}

__global__ void k_final(float* out) {
    float dec = (g_dcnt > 0.f) ? (g_dloss / g_dcnt) : 0.f;
    out[0] = g_click / (float)(Bz * Dz * Sz) + dec;
}

// ---------------- host side ----------------
static inline void launch_gemm_small(const float* A, int lda, const int* tok, const float* emb,
                                     const float* W0, const float* W1, int ldw,
                                     const float* b0, const float* b1,
                                     float* C, int ldc, int M, int N, int K,
                                     int lanes, int half, int acc)
{
    dim3 grid(N / 64, (M + 63) / 64);
    gemm_nt<<<grid, 256>>>(A, lda, tok, emb, W0, W1, ldw, b0, b1,
                           C, ldc, M, N, K, lanes, half, acc);
}
static inline void launch_gemm_big(const float* A, int lda, const int* tok, const float* emb,
                                   const float* W0, const float* W1, int ldw,
                                   const float* b0, const float* b1,
                                   float* C, int ldc, int M, int N, int K,
                                   int lanes, int half, int acc,
                                   const int* cntF, const int* cntB)
{
    dim3 grid(N / 128, (M + 127) / 128);
    gemm_nt_big<<<grid, 256>>>(A, lda, tok, emb, W0, W1, ldw, b0, b1,
                               C, ldc, M, N, K, lanes, half, acc, cntF, cntB);
}

#define GETSYM(var, sym) do { void* p_; cudaGetSymbolAddress(&p_, sym); var = (decltype(var))p_; } while (0)

extern "C" void kernel_launch(void* const* d_in, const int* in_sizes, int n_in,
                              void* d_out, int out_size)
{
    (void)in_sizes; (void)n_in; (void)out_size;
    const int*   sq     = (const int*)d_in[0];
    const int*   sql    = (const int*)d_in[1];
    const int*   rd     = (const int*)d_in[2];
    const int*   rdl    = (const int*)d_in[3];
    const float* labels = (const float*)d_in[4];
    const float* emb    = (const float*)d_in[5];
    const float* qWihf  = (const float*)d_in[6];
    const float* qWhhf  = (const float*)d_in[7];
    const float* qbf    = (const float*)d_in[8];
    const float* qWihb  = (const float*)d_in[9];
    const float* qWhhb  = (const float*)d_in[10];
    const float* qbb    = (const float*)d_in[11];
    const float* dWihf  = (const float*)d_in[12];
    const float* dWhhf  = (const float*)d_in[13];
    const float* dbf    = (const float*)d_in[14];
    const float* dWihb  = (const float*)d_in[15];
    const float* dWhhb  = (const float*)d_in[16];
    const float* dbb    = (const float*)d_in[17];
    const float* sWih   = (const float*)d_in[18];
    const float* sWhh   = (const float*)d_in[19];
    const float* sb     = (const float*)d_in[20];
    const float* projW  = (const float*)d_in[21];
    const float* projb  = (const float*)d_in[22];
    const float* decWih = (const float*)d_in[23];
    const float* decWhh = (const float*)d_in[24];
    const float* decb   = (const float*)d_in[25];
    const float* outW   = (const float*)d_in[26];
    const float* outb   = (const float*)d_in[27];

    float *qGates, *dGates, *decGates, *logits;
    float *qh, *qc, *qrmax, *dh, *dc, *drmax, *encq, *sessH, *sessC;
    int *qTok, *dTok, *decTok;
    int *cntF, *cntB, *slenD;
    float *decH, *comb, *sgates;
    GETSYM(qGates, g_qGates);     GETSYM(dGates, g_dGates);
    GETSYM(decGates, g_decGates); GETSYM(logits, g_logits);
    GETSYM(qh, g_qh); GETSYM(qc, g_qc); GETSYM(qrmax, g_qrmax);
    GETSYM(dh, g_dh); GETSYM(dc, g_dc); GETSYM(drmax, g_drmax);
    GETSYM(encq, g_encq); GETSYM(sessH, g_sessH); GETSYM(sessC, g_sessC);
    GETSYM(qTok, g_qTok); GETSYM(dTok, g_dTok); GETSYM(decTok, g_decTok);
    GETSYM(cntF, g_cntF); GETSYM(cntB, g_cntB); GETSYM(slenD, g_slenD);
    GETSYM(decH, g_decH); GETSYM(comb, g_comb); GETSYM(sgates, g_sgates);

    const int TPB = 256;
    // ---- init state ----
    k_fill<<<(QLANES * Hqz + TPB - 1) / TPB, TPB>>>(qh, QLANES * Hqz, 0.f);
    k_fill<<<(QLANES * Hqz + TPB - 1) / TPB, TPB>>>(qc, QLANES * Hqz, 0.f);
    k_fill<<<(QLANES * Hqz + TPB - 1) / TPB, TPB>>>(qrmax, QLANES * Hqz, NEGF);
    k_fill<<<(DLANES * Hdz + TPB - 1) / TPB, TPB>>>(dh, DLANES * Hdz, 0.f);
    k_fill<<<(DLANES * Hdz + TPB - 1) / TPB, TPB>>>(dc, DLANES * Hdz, 0.f);
    k_fill<<<(DLANES * Hdz + TPB - 1) / TPB, TPB>>>(drmax, DLANES * Hdz, NEGF);
    k_fill<<<(Bz * Hsz + TPB - 1) / TPB, TPB>>>(sessH, Bz * Hsz, 0.f);
    k_fill<<<(Bz * Hsz + TPB - 1) / TPB, TPB>>>(sessC, Bz * Hsz, 0.f);
    k_zero_scal<<<1, 1>>>();

    // ---- doc length sort, then token tables ----
    k_sortD<<<1, 256>>>(rdl);
    k_qtok<<<(QLz * QLANES + TPB - 1) / TPB, TPB>>>(sq);
    k_dtok<<<(DLz * DLANES + TPB - 1) / TPB, TPB>>>(rd);
    k_dectok<<<(TDEC * NDEC + TPB - 1) / TPB, TPB>>>(sq);

    // ---- x-part gate precompute (gather GEMMs) ----
    launch_gemm_big(nullptr, 0, qTok, emb, qWihf, qWihb, Ez, qbf, qbb,
                    qGates, 4 * Hqz, QLz * QLANES, 4 * Hqz, Ez,
                    QLANES, NQ, 0, nullptr, nullptr);
    launch_gemm_big(nullptr, 0, dTok, emb, dWihf, dWihb, Ez, dbf, dbb,
                    dGates, 4 * Hdz, DLz * DLANES, 4 * Hdz, Ez,
                    DLANES, NDOC, 0, cntF, cntB);
    launch_gemm_big(nullptr, 0, decTok, emb, decWih, decWih, Ez, decb, decb,
                    decGates, 4 * Hsz, TDEC * NDEC, 4 * Hsz, Ez,
                    TDEC * NDEC, TDEC * NDEC, 0, nullptr, nullptr);

    // ---- query BiLSTM (small GEMM: M=256) ----
    for (int t = 0; t < QLz; t++) {
        float* gt = qGates + (size_t)t * QLANES * 4 * Hqz;
        launch_gemm_small(qh, Hqz, nullptr, nullptr, qWhhf, qWhhb, Hqz, nullptr, nullptr,
                          gt, 4 * Hqz, QLANES, 4 * Hqz, Hqz, QLANES, NQ, 1);
        k_enc_step<<<(QLANES * Hqz + TPB - 1) / TPB, TPB>>>(gt, qh, qc, qrmax,
                                                            sql, QLANES, NQ, Hqz, QLz, t);
    }

    // ---- doc BiLSTM (big GEMM with active-count skip) ----
    for (int t = 0; t < DLz; t++) {
        float* gt = dGates + (size_t)t * DLANES * 4 * Hdz;
        launch_gemm_big(dh, Hdz, nullptr, nullptr, dWhhf, dWhhb, Hdz, nullptr, nullptr,
                        gt, 4 * Hdz, DLANES, 4 * Hdz, Hdz,
                        DLANES, NDOC, 1, cntF + t, cntB + t);
        k_enc_step<<<(DLANES * Hdz + TPB - 1) / TPB, TPB>>>(gt, dh, dc, drmax,
                                                            slenD, DLANES, NDOC, Hdz, DLz, t);
    }

    // ---- assemble encoder outputs ----
    k_build_encq<<<(NQ * 2 * Hqz + TPB - 1) / TPB, TPB>>>();
    k_build_encd<<<(NDOC * 2 * Hdz + TPB - 1) / TPB, TPB>>>();

    // ---- session loop ----
    for (int s = 0; s < Sz; s++) {
        launch_gemm_small(encq + s * (2 * Hqz), Sz * 2 * Hqz, nullptr, nullptr,
                          projW, projW, 2 * Hqz + Hsz, projb, projb,
                          comb, Hsz, Bz, Hsz, 2 * Hqz, Bz, Bz, 0);
        launch_gemm_small(sessH, Hsz, nullptr, nullptr,
                          projW + 2 * Hqz, projW + 2 * Hqz, 2 * Hqz + Hsz, nullptr, nullptr,
                          comb, Hsz, Bz, Hsz, Hsz, Bz, Bz, 1);
        k_score_bce<<<Bz, 256>>>(labels, s);
        launch_gemm_small(encq + s * (2 * Hqz), Sz * 2 * Hqz, nullptr, nullptr,
                          sWih, sWih, 2 * Hqz, sb, sb,
                          sgates, 4 * Hsz, Bz, 4 * Hsz, 2 * Hqz, Bz, Bz, 0);
        launch_gemm_small(sessH, Hsz, nullptr, nullptr, sWhh, sWhh, Hsz, nullptr, nullptr,
                          sgates, 4 * Hsz, Bz, 4 * Hsz, Hsz, Bz, Bz, 1);
        k_sess_cell<<<(Bz * Hsz + TPB - 1) / TPB, TPB>>>(s);
    }

    // ---- decoder ----
    k_dec_init<<<(NDEC * Hsz + TPB - 1) / TPB, TPB>>>();
    for (int t = 0; t < TDEC; t++) {
        float* gt = decGates + (size_t)t * NDEC * 4 * Hsz;
        launch_gemm_small(decH, Hsz, nullptr, nullptr, decWhh, decWhh, Hsz, nullptr, nullptr,
                          gt, 4 * Hsz, NDEC, 4 * Hsz, Hsz, NDEC, NDEC, 1);
        k_dec_cell<<<(NDEC * Hsz + TPB - 1) / TPB, TPB>>>(gt);
        launch_gemm_big(decH, Hsz, nullptr, nullptr, outW, outW, Hsz, outb, outb,
                        logits, Vz, NDEC, Vz, Hsz, NDEC, NDEC, 0, nullptr, nullptr);
        k_nll<<<NDEC, 256>>>(sql, t);
    }

    k_final<<<1, 1>>>((float*)d_out);
}